// round 15
// baseline (speedup 1.0000x reference)
#include <cuda_runtime.h>
#include <cuda_fp16.h>
#include <cstdint>

// Shapes (fixed):
//  input_tensor: (8, 3, 256, 256)   d_in[0]
//  conv1_w:      (8, 3, 1, 1)       d_in[1]
//  conv1_b:      (8,)               d_in[2]
//  offset_w:     (27, 8, 3, 3)      d_in[3]
//  offset_b:     (27,)              d_in[4]
//  dcn_w:        (512, 8, 3, 3)     d_in[5]
//  out:          (8, 512, 128, 128) float32

#define NB   8
#define HH   256
#define WW   256
#define HO   128
#define WO   128
#define NPOS (NB * HO * WO)      // 131072
#define TPOS 64
#define NT   (NPOS / TPOS)       // 2048
#define GRID 296
#define NTHR 384                 // 8 consumer warps + 4 sampler warps

typedef unsigned long long u64;

__device__ __half g_y[NB * HH * WW * 8];    // fp16 channels-last, 8 MB

// smem layout (bytes). K=72 rows of 144 B (36 words: conflict-free ldmatrix).
#define RSTRIDE 144
#define SM_W    0                   // W [512][72] fp16              73728
#define SM_A    73728               // A double buf [64][72]         2*9216
#define ABUF    9216
#define SM_P    92160               // P patch [64 pos][72] fp16     9216
#define SM_WOM  101376              // W_om [32 oc][72] fp16         4608
#define SM_OMS  105984              // om_s [28 oc][68 pos] f32      7616
#define SM_BIAS 113600              // offset bias 27 f32 (pad 128)
#define SM_TOTAL 113728

// ------------------------------------------------------------------ PTX utils
__device__ __forceinline__ uint32_t smem_u32(const void* p) {
    uint32_t a;
    asm("{ .reg .u64 t; cvta.to.shared.u64 t, %1; cvt.u32.u64 %0, t; }" : "=r"(a) : "l"(p));
    return a;
}
__device__ __forceinline__ void ldsm4(uint32_t* r, uint32_t a) {
    asm volatile("ldmatrix.sync.aligned.m8n8.x4.shared.b16 {%0,%1,%2,%3}, [%4];"
        : "=r"(r[0]), "=r"(r[1]), "=r"(r[2]), "=r"(r[3]) : "r"(a));
}
__device__ __forceinline__ void ldsm2(uint32_t* r, uint32_t a) {
    asm volatile("ldmatrix.sync.aligned.m8n8.x2.shared.b16 {%0,%1}, [%2];"
        : "=r"(r[0]), "=r"(r[1]) : "r"(a));
}
__device__ __forceinline__ void mma_f16(float* d, const uint32_t* a, const uint32_t* b) {
    asm volatile("mma.sync.aligned.m16n8k16.row.col.f32.f16.f16.f32 "
        "{%0,%1,%2,%3}, {%4,%5,%6,%7}, {%8,%9}, {%0,%1,%2,%3};"
        : "+f"(d[0]), "+f"(d[1]), "+f"(d[2]), "+f"(d[3])
        : "r"(a[0]), "r"(a[1]), "r"(a[2]), "r"(a[3]), "r"(b[0]), "r"(b[1]));
}
__device__ __forceinline__ void mma_f16_k8(float* d, const uint32_t* a, uint32_t b) {
    asm volatile("mma.sync.aligned.m16n8k8.row.col.f32.f16.f16.f32 "
        "{%0,%1,%2,%3}, {%4,%5}, {%6}, {%0,%1,%2,%3};"
        : "+f"(d[0]), "+f"(d[1]), "+f"(d[2]), "+f"(d[3])
        : "r"(a[0]), "r"(a[1]), "r"(b));
}
__device__ __forceinline__ float2 h2f(uint32_t h) {
    __half2 v = *(__half2*)&h;
    return __half22float2(v);
}
__device__ __forceinline__ void cp_async16(uint32_t dst, const void* src, uint32_t src_sz) {
    asm volatile("cp.async.cg.shared.global [%0], [%1], 16, %2;"
        :: "r"(dst), "l"(src), "r"(src_sz) : "memory");
}
#define CP_COMMIT() asm volatile("cp.async.commit_group;" ::: "memory")
#define CP_WAIT0()  asm volatile("cp.async.wait_group 0;" ::: "memory")
#define BAR_SYNC(id, cnt) \
    asm volatile("bar.sync %0, %1;" :: "r"(id), "r"(cnt) : "memory")
#define BAR_ARRIVE(id, cnt) \
    asm volatile("bar.arrive %0, %1;" :: "r"(id), "r"(cnt) : "memory")

// ---------------- kernel 1: 1x1 conv (3->8) + leaky relu -> fp16 channels-last ---------
__global__ void k_conv1(const float* __restrict__ x,
                        const float* __restrict__ w1,
                        const float* __restrict__ b1) {
    int idx4 = blockIdx.x * blockDim.x + threadIdx.x;
    if (idx4 >= NB * HH * WW / 4) return;
    int base = idx4 << 2;
    int n  = base >> 16;
    int hw = base & 0xFFFF;
    float4 c0 = *(const float4*)(x + (size_t)(n * 3 + 0) * 65536 + hw);
    float4 c1 = *(const float4*)(x + (size_t)(n * 3 + 1) * 65536 + hw);
    float4 c2 = *(const float4*)(x + (size_t)(n * 3 + 2) * 65536 + hw);
    float w[24], bb[8];
#pragma unroll
    for (int i = 0; i < 24; i++) w[i] = __ldg(&w1[i]);
#pragma unroll
    for (int i = 0; i < 8; i++) bb[i] = __ldg(&b1[i]);
    float px0[4] = {c0.x, c0.y, c0.z, c0.w};
    float px1[4] = {c1.x, c1.y, c1.z, c1.w};
    float px2[4] = {c2.x, c2.y, c2.z, c2.w};
#pragma unroll
    for (int p = 0; p < 4; p++) {
        uint32_t h[4];
#pragma unroll
        for (int cp = 0; cp < 4; cp++) {
            float t0 = w[(2 * cp) * 3 + 0] * px0[p] + w[(2 * cp) * 3 + 1] * px1[p] +
                       w[(2 * cp) * 3 + 2] * px2[p] + bb[2 * cp];
            float t1 = w[(2 * cp + 1) * 3 + 0] * px0[p] + w[(2 * cp + 1) * 3 + 1] * px1[p] +
                       w[(2 * cp + 1) * 3 + 2] * px2[p] + bb[2 * cp + 1];
            t0 = t0 >= 0.f ? t0 : 0.1f * t0;
            t1 = t1 >= 0.f ? t1 : 0.1f * t1;
            __half2 hh = __floats2half2_rn(t0, t1);
            h[cp] = *(uint32_t*)&hh;
        }
        *(uint4*)(g_y + (size_t)(base + p) * 8) = make_uint4(h[0], h[1], h[2], h[3]);
    }
}

// ---------------- kernel 2: warp-specialized fused DCN -------------------------------
// Warps 0-7 (consumers): main GEMM M=512ch x N=64pos x K=72 + epilogue, in 4
// 16-ch quarter-tiles. Warps 8-11 (samplers): each FULLY OWNS 16 positions:
// P cp.async -> om GEMM -> gathers, with only __syncwarp internally (no cross-
// sampler barriers). Producer/consumer handshake via parity named barriers.

// sampler-own P task t (0..143): tap = t>>4, pos = sw*16 + (t&15)
__device__ __forceinline__ void cp_p_own(uint32_t sb, int n2, int spbn, int sw, int t) {
    int tap = t >> 4, pos = sw * 16 + (t & 15);
    int sp = spbn + pos;
    int ho = sp >> 7, wo = sp & 127;
    int hy = 2 * ho - 1 + tap / 3;
    int wx = 2 * wo - 1 + tap % 3;
    bool ok = ((unsigned)hy < HH) && ((unsigned)wx < WW);
    int hyc = min(max(hy, 0), HH - 1);
    int wxc = min(max(wx, 0), WW - 1);
    const void* src = g_y + ((size_t)((n2 * HH + hyc) * WW + wxc)) * 8;
    uint32_t dst = sb + SM_P + (uint32_t)(pos * RSTRIDE + tap * 16);
    cp_async16(dst, src, ok ? 16u : 0u);
}

// om GEMM: sampler warp sw computes 32 oc x its own 16 pos.
__device__ __forceinline__ void om_gemm(uint32_t sb, char* smem, int sw, int lane) {
    int g = lane >> 2, tg = lane & 3;
    float aco[2][2][4];
#pragma unroll
    for (int mt = 0; mt < 2; mt++)
#pragma unroll
        for (int nt = 0; nt < 2; nt++)
#pragma unroll
            for (int r = 0; r < 4; r++) aco[mt][nt][r] = 0.f;
    uint32_t wa = sb + SM_WOM + (uint32_t)((lane & 15) * RSTRIDE) + ((lane >> 4) << 4);
    uint32_t bp = sb + SM_P +
                  (uint32_t)((sw * 16 + (lane & 7) + ((lane >> 4) << 3)) * RSTRIDE) +
                  (((lane >> 3) & 1) << 4);
#pragma unroll
    for (int ks = 0; ks < 4; ks++) {
        uint32_t a0[4], a1[4], bo[4];
        ldsm4(a0, wa + ks * 32);
        ldsm4(a1, wa + (uint32_t)(16 * RSTRIDE) + ks * 32);
        ldsm4(bo, bp + ks * 32);
        mma_f16(aco[0][0], a0, bo);
        mma_f16(aco[0][1], a0, bo + 2);
        mma_f16(aco[1][0], a1, bo);
        mma_f16(aco[1][1], a1, bo + 2);
    }
    // k8 tail (kk 64..71)
    {
        uint32_t a0t[2], a1t[2], bt[2];
        ldsm2(a0t, wa + 128);
        ldsm2(a1t, wa + (uint32_t)(16 * RSTRIDE) + 128);
        uint32_t btp = sb + SM_P +
                       (uint32_t)((sw * 16 + (lane & 7) + (((lane >> 3) & 1) << 3)) * RSTRIDE);
        ldsm2(bt, btp + 128);
        mma_f16_k8(aco[0][0], a0t, bt[0]);
        mma_f16_k8(aco[0][1], a0t, bt[1]);
        mma_f16_k8(aco[1][0], a1t, bt[0]);
        mma_f16_k8(aco[1][1], a1t, bt[1]);
    }

    float* om_s = (float*)(smem + SM_OMS);
    const float* bias = (const float*)(smem + SM_BIAS);
#pragma unroll
    for (int mt = 0; mt < 2; mt++)
#pragma unroll
        for (int r = 0; r < 2; r++) {
            int oc = mt * 16 + g + 8 * r;
            if (oc < 27) {
#pragma unroll
                for (int nt = 0; nt < 2; nt++)
#pragma unroll
                    for (int c = 0; c < 2; c++) {
                        int pos = sw * 16 + nt * 8 + 2 * tg + c;
                        float v = aco[mt][nt][2 * r + c] + bias[oc];
                        if (oc >= 18) v = 1.f / (1.f + __expf(-v));
                        om_s[oc * 68 + pos] = v;
                    }
            }
        }
}

// consumer quarter-tile MMA: 16 ch x 64 pos, K=72
__device__ __forceinline__ void mma_quarter(uint32_t wa, uint32_t ba4, uint32_t bat,
                                            float acc[8][4]) {
#pragma unroll
    for (int ks = 0; ks < 4; ks++) {
        uint32_t a[4];
        ldsm4(a, wa + ks * 32);
#pragma unroll
        for (int p = 0; p < 4; p++) {
            uint32_t b4[4];
            ldsm4(b4, ba4 + (uint32_t)(p * 16 * RSTRIDE) + ks * 32);
            mma_f16(acc[2 * p],     a, b4);
            mma_f16(acc[2 * p + 1], a, b4 + 2);
        }
    }
    uint32_t at[2];
    ldsm2(at, wa + 128);
#pragma unroll
    for (int p = 0; p < 4; p++) {
        uint32_t bt[2];
        ldsm2(bt, bat + (uint32_t)(p * 16 * RSTRIDE) + 128);
        mma_f16_k8(acc[2 * p],     at, bt[0]);
        mma_f16_k8(acc[2 * p + 1], at, bt[1]);
    }
}

// epilogue for one quarter: shfl-assembled STG.128
__device__ __forceinline__ void epi_quarter(const float acc[8][4], float* out,
                                            int n, int spbase, int q,
                                            int wid, int lane) {
    int g = lane >> 2, tg = lane & 3;
    int odd = tg & 1;
    int ch0 = wid * 64 + q * 16 + g;
#pragma unroll
    for (int r = 0; r < 2; r++) {
        float* rowp = out + (size_t)(n * 512 + ch0 + 8 * r) * 16384 + spbase;
#pragma unroll
        for (int p = 0; p < 4; p++) {
            int nt0 = 2 * p, nt1 = 2 * p + 1;
            float a0x = acc[nt0][2 * r], a0y = acc[nt0][2 * r + 1];
            float a1x = acc[nt1][2 * r], a1y = acc[nt1][2 * r + 1];
            u64 send = odd
                ? (((u64)__float_as_uint(a0y) << 32) | __float_as_uint(a0x))
                : (((u64)__float_as_uint(a1y) << 32) | __float_as_uint(a1x));
            u64 recv = __shfl_xor_sync(0xffffffffu, send, 1);
            float rx = __uint_as_float((uint32_t)recv);
            float ry = __uint_as_float((uint32_t)(recv >> 32));
            float4 v = odd ? make_float4(rx, ry, a1x, a1y)
                           : make_float4(a0x, a0y, rx, ry);
            int col = (odd ? nt1 : nt0) * 8 + (tg >> 1) * 4;
            __stcs((float4*)(rowp + col), v);
        }
    }
}

// sampler-own gather task t (0..143): k = t>>4, pos = sw*16 + (t&15)
__device__ __forceinline__ void gather_own(const float* om_s, int n2, int spbn,
                                           int sw, int t, char* bufn) {
    int k = t >> 4, pos = sw * 16 + (t & 15);
    float dy = om_s[(2 * k) * 68 + pos];
    float dx = om_s[(2 * k + 1) * 68 + pos];
    float m  = om_s[(18 + k) * 68 + pos];
    int sp = spbn + pos;
    int ho = sp >> 7, wo = sp & 127;
    int ky = k / 3, kx = k - ky * 3;
    float py = (float)(2 * ho - 1 + ky) + dy;
    float px = (float)(2 * wo - 1 + kx) + dx;
    float y0f = floorf(py), x0f = floorf(px);
    float fy = py - y0f, fx = px - x0f;
    int y0 = (int)y0f, x0 = (int)x0f;
    uint4 q[4];
    float w4[4];
#pragma unroll
    for (int oy = 0; oy < 2; oy++) {
        int yy = y0 + oy;
        float wy = (oy ? fy : 1.f - fy) * ((unsigned)yy < HH ? 1.f : 0.f);
        int yc = min(max(yy, 0), HH - 1);
#pragma unroll
        for (int ox = 0; ox < 2; ox++) {
            int xx = x0 + ox;
            float wgt = wy * (ox ? fx : 1.f - fx) * ((unsigned)xx < WW ? 1.f : 0.f);
            int xc = min(max(xx, 0), WW - 1);
            w4[oy * 2 + ox] = wgt;
            q[oy * 2 + ox] = *(const uint4*)(g_y + ((size_t)((n2 * HH + yc) * WW + xc)) * 8);
        }
    }
    float a[8] = {0, 0, 0, 0, 0, 0, 0, 0};
#pragma unroll
    for (int cor = 0; cor < 4; cor++) {
        float wgt = w4[cor];
        float2 f0 = h2f(q[cor].x), f1 = h2f(q[cor].y);
        float2 f2 = h2f(q[cor].z), f3 = h2f(q[cor].w);
        a[0] += wgt * f0.x; a[1] += wgt * f0.y; a[2] += wgt * f1.x; a[3] += wgt * f1.y;
        a[4] += wgt * f2.x; a[5] += wgt * f2.y; a[6] += wgt * f3.x; a[7] += wgt * f3.y;
    }
    uint32_t h4[4];
#pragma unroll
    for (int i = 0; i < 4; i++) {
        __half2 h = __floats2half2_rn(a[2 * i] * m, a[2 * i + 1] * m);
        h4[i] = *(uint32_t*)&h;
    }
    *(uint4*)(bufn + pos * RSTRIDE + k * 16) = make_uint4(h4[0], h4[1], h4[2], h4[3]);
}

// full sampler pipeline for one tile (warp-private; __syncwarp only)
__device__ __forceinline__ void sample_tile(uint32_t sb, char* smem, const float* om_s,
                                            int n2, int spbn, int sw, int lane,
                                            char* bufn) {
#pragma unroll
    for (int r = 0; r < 5; r++) {
        int t = r * 32 + lane;
        if (t < 144) cp_p_own(sb, n2, spbn, sw, t);
    }
    CP_COMMIT();
    CP_WAIT0();
    __syncwarp();
    om_gemm(sb, smem, sw, lane);
    __syncwarp();
#pragma unroll
    for (int r = 0; r < 5; r++) {
        int t = r * 32 + lane;
        if (t < 144) gather_own(om_s, n2, spbn, sw, t, bufn);
    }
}

__global__ void __launch_bounds__(NTHR, 2)
k_dcn(const float* __restrict__ dw,
      const float* __restrict__ ow, const float* __restrict__ ob,
      float* __restrict__ out) {
    extern __shared__ char smem[];
    uint32_t sb = smem_u32(smem);
    int tid = threadIdx.x, lane = tid & 31, wid = tid >> 5;
    bool cons = (wid < 8);
    int sw = wid - 8;

    // W fill: W[ch][kk] fp16, kk = tap*8 + c
    for (int i = tid; i < 512 * 72; i += NTHR) {
        int ch = i / 72, j = i - ch * 72;      // j = c*9 + tap
        int c = j / 9, k = j - c * 9;
        *(__half*)(smem + SM_W + ch * RSTRIDE + (k * 8 + c) * 2) = __float2half_rn(dw[i]);
    }
    // W_om: zero pad rows then fill [oc][kk = tap*8 + ic]
    for (int i = tid; i < 4608 / 16; i += NTHR)
        ((uint4*)(smem + SM_WOM))[i] = make_uint4(0, 0, 0, 0);
    __syncthreads();
    for (int i = tid; i < 27 * 72; i += NTHR) {
        int oc = i / 72, j = i - oc * 72;      // j = ic*9 + tap
        int ic = j / 9, tap = j - ic * 9;
        *(__half*)(smem + SM_WOM + oc * RSTRIDE + (tap * 8 + ic) * 2) = __float2half_rn(ow[i]);
    }
    if (tid < 27) ((float*)(smem + SM_BIAS))[tid] = ob[tid];

    uint32_t wa_base = sb + SM_W + (uint32_t)(((wid & 7) * 64 + (lane & 15)) * RSTRIDE) +
                       ((lane >> 4) << 4);
    uint32_t ba4_base = sb + SM_A + (uint32_t)(((lane & 7) + ((lane >> 4) << 3)) * RSTRIDE) +
                        (((lane >> 3) & 1) << 4);
    uint32_t bat_base = sb + SM_A + (uint32_t)(((lane & 7) + (((lane >> 3) & 1) << 3)) * RSTRIDE);
    const float* om_s = (const float*)(smem + SM_OMS);
    __syncthreads();

    // ---- prologue: samplers build A buf0 for tile = blockIdx.x ----
    if (!cons) {
        int pb = blockIdx.x << 6;
        sample_tile(sb, smem, om_s, pb >> 14, pb & 16383, sw, lane, smem + SM_A);
    }
    __syncthreads();

    int i = 0;
    for (int tile = blockIdx.x; tile < NT; tile += GRID, ++i) {
        int cur = i & 1;
        if (cons) {
            if (i) BAR_SYNC(1 + cur, NTHR);             // FULL: A buf[cur] ready
            int pbase = tile << 6;
            int n = pbase >> 14;
            int spbase = pbase & 16383;
            uint32_t ba4 = ba4_base + (uint32_t)(cur * ABUF);
            uint32_t bat = bat_base + (uint32_t)(cur * ABUF);
#pragma unroll 1
            for (int q = 0; q < 4; q++) {
                float acc[8][4];
#pragma unroll
                for (int nt = 0; nt < 8; nt++)
#pragma unroll
                    for (int r = 0; r < 4; r++) acc[nt][r] = 0.f;
                mma_quarter(wa_base + (uint32_t)(q * 16 * RSTRIDE), ba4, bat, acc);
                epi_quarter(acc, out, n, spbase, q, wid, lane);
            }
            BAR_ARRIVE(4 + cur, NTHR);                  // FREE: done reading buf[cur]
        } else {
            int tp = tile + GRID;
            if (tp < NT) {
                int nxt = cur ^ 1;
                if (i) BAR_SYNC(4 + nxt, NTHR);         // FREE: buf[nxt] reusable
                int pbn = tp << 6;
                sample_tile(sb, smem, om_s, pbn >> 14, pbn & 16383, sw, lane,
                            smem + SM_A + nxt * ABUF);
                BAR_ARRIVE(1 + nxt, NTHR);              // FULL for next iteration
            }
        }
    }
}

// ---------------- launch ----------------
extern "C" void kernel_launch(void* const* d_in, const int* in_sizes, int n_in,
                              void* d_out, int out_size) {
    const float* x  = (const float*)d_in[0];
    const float* w1 = (const float*)d_in[1];
    const float* b1 = (const float*)d_in[2];
    const float* ow = (const float*)d_in[3];
    const float* ob = (const float*)d_in[4];
    const float* dw = (const float*)d_in[5];
    float* out = (float*)d_out;

    k_conv1<<<(NB * HH * WW / 4 + 255) / 256, 256>>>(x, w1, b1);

    cudaFuncSetAttribute(k_dcn, cudaFuncAttributeMaxDynamicSharedMemorySize, SM_TOTAL);
    k_dcn<<<GRID, NTHR, SM_TOTAL>>>(dw, ow, ob, out);
}

// round 16
// speedup vs baseline: 1.0801x; 1.0801x over previous
#include <cuda_runtime.h>
#include <cuda_fp16.h>
#include <cstdint>

// Shapes (fixed):
//  input_tensor: (8, 3, 256, 256)   d_in[0]
//  conv1_w:      (8, 3, 1, 1)       d_in[1]
//  conv1_b:      (8,)               d_in[2]
//  offset_w:     (27, 8, 3, 3)      d_in[3]
//  offset_b:     (27,)              d_in[4]
//  dcn_w:        (512, 8, 3, 3)     d_in[5]
//  out:          (8, 512, 128, 128) float32

#define NB   8
#define HH   256
#define WW   256
#define HO   128
#define WO   128
#define NPOS (NB * HO * WO)      // 131072
#define TPOS 64
#define NT   (NPOS / TPOS)       // 2048
#define GRID 296
#define NTHR 384                 // 8 consumer warps + 4 sampler warps

typedef unsigned long long u64;

__device__ __half g_y[NB * HH * WW * 8];    // fp16 channels-last, 8 MB

// smem layout (bytes). K=72 rows of 144 B (36 words: conflict-free ldmatrix).
#define RSTRIDE 144
#define SM_W    0                   // W [512][72] fp16              73728
#define SM_A    73728               // A double buf [64][72]         2*9216
#define ABUF    9216
#define SM_P    92160               // P patch [64 pos][72] fp16     9216
#define SM_WOM  101376              // W_om [32 oc][72] fp16         4608
#define SM_OMS  105984              // om_s [28 oc][68 pos] f32      7616
#define SM_BIAS 113600              // offset bias 27 f32 (pad 128)
#define SM_TOTAL 113728

// ------------------------------------------------------------------ PTX utils
__device__ __forceinline__ uint32_t smem_u32(const void* p) {
    uint32_t a;
    asm("{ .reg .u64 t; cvta.to.shared.u64 t, %1; cvt.u32.u64 %0, t; }" : "=r"(a) : "l"(p));
    return a;
}
__device__ __forceinline__ void ldsm4(uint32_t* r, uint32_t a) {
    asm volatile("ldmatrix.sync.aligned.m8n8.x4.shared.b16 {%0,%1,%2,%3}, [%4];"
        : "=r"(r[0]), "=r"(r[1]), "=r"(r[2]), "=r"(r[3]) : "r"(a));
}
__device__ __forceinline__ void ldsm2(uint32_t* r, uint32_t a) {
    asm volatile("ldmatrix.sync.aligned.m8n8.x2.shared.b16 {%0,%1}, [%2];"
        : "=r"(r[0]), "=r"(r[1]) : "r"(a));
}
__device__ __forceinline__ void mma_f16(float* d, const uint32_t* a, const uint32_t* b) {
    asm volatile("mma.sync.aligned.m16n8k16.row.col.f32.f16.f16.f32 "
        "{%0,%1,%2,%3}, {%4,%5,%6,%7}, {%8,%9}, {%0,%1,%2,%3};"
        : "+f"(d[0]), "+f"(d[1]), "+f"(d[2]), "+f"(d[3])
        : "r"(a[0]), "r"(a[1]), "r"(a[2]), "r"(a[3]), "r"(b[0]), "r"(b[1]));
}
__device__ __forceinline__ void mma_f16_k8(float* d, const uint32_t* a, uint32_t b) {
    asm volatile("mma.sync.aligned.m16n8k8.row.col.f32.f16.f16.f32 "
        "{%0,%1,%2,%3}, {%4,%5}, {%6}, {%0,%1,%2,%3};"
        : "+f"(d[0]), "+f"(d[1]), "+f"(d[2]), "+f"(d[3])
        : "r"(a[0]), "r"(a[1]), "r"(b));
}
__device__ __forceinline__ float2 h2f(uint32_t h) {
    __half2 v = *(__half2*)&h;
    return __half22float2(v);
}
__device__ __forceinline__ void cp_async16(uint32_t dst, const void* src, uint32_t src_sz) {
    asm volatile("cp.async.cg.shared.global [%0], [%1], 16, %2;"
        :: "r"(dst), "l"(src), "r"(src_sz) : "memory");
}
#define CP_COMMIT() asm volatile("cp.async.commit_group;" ::: "memory")
#define CP_WAIT0()  asm volatile("cp.async.wait_group 0;" ::: "memory")
#define BAR_SYNC(id, cnt) \
    asm volatile("bar.sync %0, %1;" :: "r"(id), "r"(cnt) : "memory")
#define BAR_ARRIVE(id, cnt) \
    asm volatile("bar.arrive %0, %1;" :: "r"(id), "r"(cnt) : "memory")

// ---------------- kernel 1: 1x1 conv (3->8) + leaky relu -> fp16 channels-last ---------
__global__ void k_conv1(const float* __restrict__ x,
                        const float* __restrict__ w1,
                        const float* __restrict__ b1) {
    int idx4 = blockIdx.x * blockDim.x + threadIdx.x;
    if (idx4 >= NB * HH * WW / 4) return;
    int base = idx4 << 2;
    int n  = base >> 16;
    int hw = base & 0xFFFF;
    float4 c0 = *(const float4*)(x + (size_t)(n * 3 + 0) * 65536 + hw);
    float4 c1 = *(const float4*)(x + (size_t)(n * 3 + 1) * 65536 + hw);
    float4 c2 = *(const float4*)(x + (size_t)(n * 3 + 2) * 65536 + hw);
    float w[24], bb[8];
#pragma unroll
    for (int i = 0; i < 24; i++) w[i] = __ldg(&w1[i]);
#pragma unroll
    for (int i = 0; i < 8; i++) bb[i] = __ldg(&b1[i]);
    float px0[4] = {c0.x, c0.y, c0.z, c0.w};
    float px1[4] = {c1.x, c1.y, c1.z, c1.w};
    float px2[4] = {c2.x, c2.y, c2.z, c2.w};
#pragma unroll
    for (int p = 0; p < 4; p++) {
        uint32_t h[4];
#pragma unroll
        for (int cp = 0; cp < 4; cp++) {
            float t0 = w[(2 * cp) * 3 + 0] * px0[p] + w[(2 * cp) * 3 + 1] * px1[p] +
                       w[(2 * cp) * 3 + 2] * px2[p] + bb[2 * cp];
            float t1 = w[(2 * cp + 1) * 3 + 0] * px0[p] + w[(2 * cp + 1) * 3 + 1] * px1[p] +
                       w[(2 * cp + 1) * 3 + 2] * px2[p] + bb[2 * cp + 1];
            t0 = t0 >= 0.f ? t0 : 0.1f * t0;
            t1 = t1 >= 0.f ? t1 : 0.1f * t1;
            __half2 hh = __floats2half2_rn(t0, t1);
            h[cp] = *(uint32_t*)&hh;
        }
        *(uint4*)(g_y + (size_t)(base + p) * 8) = make_uint4(h[0], h[1], h[2], h[3]);
    }
}

// ---------------- kernel 2: warp-specialized fused DCN -------------------------------
// Warps 0-7 (consumers): main GEMM M=512ch x N=64pos x K=72, in 4 balanced
// quarter-tiles of 32ch x 32pos (acc 32 regs; A and B fragments each re-read 2x
// instead of B 4x). Warps 8-11 (samplers): P cp.async -> om GEMM -> gathers
// (R14 striped task maps). Producer/consumer via parity named barriers.

// P task j (0..575): tap = j>>6, pos = j&63 (lanes take consecutive positions)
__device__ __forceinline__ void cp_p(uint32_t sb, int n2, int spbn, int j) {
    int tap = j >> 6, pos = j & 63;
    int sp = spbn + pos;
    int ho = sp >> 7, wo = sp & 127;
    int hy = 2 * ho - 1 + tap / 3;
    int wx = 2 * wo - 1 + tap % 3;
    bool ok = ((unsigned)hy < HH) && ((unsigned)wx < WW);
    int hyc = min(max(hy, 0), HH - 1);
    int wxc = min(max(wx, 0), WW - 1);
    const void* src = g_y + ((size_t)((n2 * HH + hyc) * WW + wxc)) * 8;
    uint32_t dst = sb + SM_P + (uint32_t)(pos * RSTRIDE + tap * 16);
    cp_async16(dst, src, ok ? 16u : 0u);
}

// om GEMM: sampler warp sw computes 32 oc x 16 pos (pos sw*16..sw*16+15).
__device__ __forceinline__ void om_gemm(uint32_t sb, char* smem, int sw, int lane) {
    int g = lane >> 2, tg = lane & 3;
    float aco[2][2][4];
#pragma unroll
    for (int mt = 0; mt < 2; mt++)
#pragma unroll
        for (int nt = 0; nt < 2; nt++)
#pragma unroll
            for (int r = 0; r < 4; r++) aco[mt][nt][r] = 0.f;
    uint32_t wa = sb + SM_WOM + (uint32_t)((lane & 15) * RSTRIDE) + ((lane >> 4) << 4);
    uint32_t bp = sb + SM_P +
                  (uint32_t)((sw * 16 + (lane & 7) + ((lane >> 4) << 3)) * RSTRIDE) +
                  (((lane >> 3) & 1) << 4);
#pragma unroll
    for (int ks = 0; ks < 4; ks++) {
        uint32_t a0[4], a1[4], bo[4];
        ldsm4(a0, wa + ks * 32);
        ldsm4(a1, wa + (uint32_t)(16 * RSTRIDE) + ks * 32);
        ldsm4(bo, bp + ks * 32);
        mma_f16(aco[0][0], a0, bo);
        mma_f16(aco[0][1], a0, bo + 2);
        mma_f16(aco[1][0], a1, bo);
        mma_f16(aco[1][1], a1, bo + 2);
    }
    // k8 tail (kk 64..71)
    {
        uint32_t a0t[2], a1t[2], bt[2];
        ldsm2(a0t, wa + 128);
        ldsm2(a1t, wa + (uint32_t)(16 * RSTRIDE) + 128);
        uint32_t btp = sb + SM_P +
                       (uint32_t)((sw * 16 + (lane & 7) + (((lane >> 3) & 1) << 3)) * RSTRIDE);
        ldsm2(bt, btp + 128);
        mma_f16_k8(aco[0][0], a0t, bt[0]);
        mma_f16_k8(aco[0][1], a0t, bt[1]);
        mma_f16_k8(aco[1][0], a1t, bt[0]);
        mma_f16_k8(aco[1][1], a1t, bt[1]);
    }

    float* om_s = (float*)(smem + SM_OMS);
    const float* bias = (const float*)(smem + SM_BIAS);
#pragma unroll
    for (int mt = 0; mt < 2; mt++)
#pragma unroll
        for (int r = 0; r < 2; r++) {
            int oc = mt * 16 + g + 8 * r;
            if (oc < 27) {
#pragma unroll
                for (int nt = 0; nt < 2; nt++)
#pragma unroll
                    for (int c = 0; c < 2; c++) {
                        int pos = sw * 16 + nt * 8 + 2 * tg + c;
                        float v = aco[mt][nt][2 * r + c] + bias[oc];
                        if (oc >= 18) v = 1.f / (1.f + __expf(-v));
                        om_s[oc * 68 + pos] = v;
                    }
            }
        }
}

// consumer balanced quarter: 32 ch x 32 pos, K=72
__device__ __forceinline__ void mma_hq(uint32_t wa, uint32_t ba4, uint32_t bat,
                                       float acc[2][4][4]) {
#pragma unroll
    for (int ks = 0; ks < 4; ks++) {
        uint32_t a0[4], a1[4];
        ldsm4(a0, wa + ks * 32);
        ldsm4(a1, wa + (uint32_t)(16 * RSTRIDE) + ks * 32);
#pragma unroll
        for (int p = 0; p < 2; p++) {
            uint32_t b4[4];
            ldsm4(b4, ba4 + (uint32_t)(p * 16 * RSTRIDE) + ks * 32);
            mma_f16(acc[0][2 * p],     a0, b4);
            mma_f16(acc[0][2 * p + 1], a0, b4 + 2);
            mma_f16(acc[1][2 * p],     a1, b4);
            mma_f16(acc[1][2 * p + 1], a1, b4 + 2);
        }
    }
    uint32_t a0t[2], a1t[2];
    ldsm2(a0t, wa + 128);
    ldsm2(a1t, wa + (uint32_t)(16 * RSTRIDE) + 128);
#pragma unroll
    for (int p = 0; p < 2; p++) {
        uint32_t bt[2];
        ldsm2(bt, bat + (uint32_t)(p * 16 * RSTRIDE) + 128);
        mma_f16_k8(acc[0][2 * p],     a0t, bt[0]);
        mma_f16_k8(acc[0][2 * p + 1], a0t, bt[1]);
        mma_f16_k8(acc[1][2 * p],     a1t, bt[0]);
        mma_f16_k8(acc[1][2 * p + 1], a1t, bt[1]);
    }
}

// epilogue for one balanced quarter: shfl-assembled STG.128
__device__ __forceinline__ void epi_hq(const float acc[2][4][4], float* out,
                                       int n, int spq, int qc,
                                       int wid, int lane) {
    int g = lane >> 2, tg = lane & 3;
    int odd = tg & 1;
#pragma unroll
    for (int mt = 0; mt < 2; mt++) {
        int ch0 = wid * 64 + qc * 32 + mt * 16 + g;
#pragma unroll
        for (int r = 0; r < 2; r++) {
            float* rowp = out + (size_t)(n * 512 + ch0 + 8 * r) * 16384 + spq;
#pragma unroll
            for (int p = 0; p < 2; p++) {
                int nt0 = 2 * p, nt1 = 2 * p + 1;
                float a0x = acc[mt][nt0][2 * r], a0y = acc[mt][nt0][2 * r + 1];
                float a1x = acc[mt][nt1][2 * r], a1y = acc[mt][nt1][2 * r + 1];
                u64 send = odd
                    ? (((u64)__float_as_uint(a0y) << 32) | __float_as_uint(a0x))
                    : (((u64)__float_as_uint(a1y) << 32) | __float_as_uint(a1x));
                u64 recv = __shfl_xor_sync(0xffffffffu, send, 1);
                float rx = __uint_as_float((uint32_t)recv);
                float ry = __uint_as_float((uint32_t)(recv >> 32));
                float4 v = odd ? make_float4(rx, ry, a1x, a1y)
                               : make_float4(a0x, a0y, rx, ry);
                int col = (odd ? nt1 : nt0) * 8 + (tg >> 1) * 4;
                __stcs((float4*)(rowp + col), v);
            }
        }
    }
}

// gather one (pos,k) task: read om_s, 4 bilinear LDGs, convert, STS
__device__ __forceinline__ void gather_task(const float* om_s, int n2, int spbn, int t,
                                            char* bufn) {
    int pos = t & 63, k = t >> 6;
    float dy = om_s[(2 * k) * 68 + pos];
    float dx = om_s[(2 * k + 1) * 68 + pos];
    float m  = om_s[(18 + k) * 68 + pos];
    int sp = spbn + pos;
    int ho = sp >> 7, wo = sp & 127;
    int ky = k / 3, kx = k - ky * 3;
    float py = (float)(2 * ho - 1 + ky) + dy;
    float px = (float)(2 * wo - 1 + kx) + dx;
    float y0f = floorf(py), x0f = floorf(px);
    float fy = py - y0f, fx = px - x0f;
    int y0 = (int)y0f, x0 = (int)x0f;
    uint4 q[4];
    float w4[4];
#pragma unroll
    for (int oy = 0; oy < 2; oy++) {
        int yy = y0 + oy;
        float wy = (oy ? fy : 1.f - fy) * ((unsigned)yy < HH ? 1.f : 0.f);
        int yc = min(max(yy, 0), HH - 1);
#pragma unroll
        for (int ox = 0; ox < 2; ox++) {
            int xx = x0 + ox;
            float wgt = wy * (ox ? fx : 1.f - fx) * ((unsigned)xx < WW ? 1.f : 0.f);
            int xc = min(max(xx, 0), WW - 1);
            w4[oy * 2 + ox] = wgt;
            q[oy * 2 + ox] = *(const uint4*)(g_y + ((size_t)((n2 * HH + yc) * WW + xc)) * 8);
        }
    }
    float a[8] = {0, 0, 0, 0, 0, 0, 0, 0};
#pragma unroll
    for (int cor = 0; cor < 4; cor++) {
        float wgt = w4[cor];
        float2 f0 = h2f(q[cor].x), f1 = h2f(q[cor].y);
        float2 f2 = h2f(q[cor].z), f3 = h2f(q[cor].w);
        a[0] += wgt * f0.x; a[1] += wgt * f0.y; a[2] += wgt * f1.x; a[3] += wgt * f1.y;
        a[4] += wgt * f2.x; a[5] += wgt * f2.y; a[6] += wgt * f3.x; a[7] += wgt * f3.y;
    }
    uint32_t h4[4];
#pragma unroll
    for (int i = 0; i < 4; i++) {
        __half2 h = __floats2half2_rn(a[2 * i] * m, a[2 * i + 1] * m);
        h4[i] = *(uint32_t*)&h;
    }
    *(uint4*)(bufn + pos * RSTRIDE + k * 16) = make_uint4(h4[0], h4[1], h4[2], h4[3]);
}

__global__ void __launch_bounds__(NTHR, 2)
k_dcn(const float* __restrict__ dw,
      const float* __restrict__ ow, const float* __restrict__ ob,
      float* __restrict__ out) {
    extern __shared__ char smem[];
    uint32_t sb = smem_u32(smem);
    int tid = threadIdx.x, lane = tid & 31, wid = tid >> 5;
    bool cons = (wid < 8);
    int sw = wid - 8;

    // W fill: W[ch][kk] fp16, kk = tap*8 + c
    for (int i = tid; i < 512 * 72; i += NTHR) {
        int ch = i / 72, j = i - ch * 72;      // j = c*9 + tap
        int c = j / 9, k = j - c * 9;
        *(__half*)(smem + SM_W + ch * RSTRIDE + (k * 8 + c) * 2) = __float2half_rn(dw[i]);
    }
    // W_om: zero pad rows then fill [oc][kk = tap*8 + ic]
    for (int i = tid; i < 4608 / 16; i += NTHR)
        ((uint4*)(smem + SM_WOM))[i] = make_uint4(0, 0, 0, 0);
    __syncthreads();
    for (int i = tid; i < 27 * 72; i += NTHR) {
        int oc = i / 72, j = i - oc * 72;      // j = ic*9 + tap
        int ic = j / 9, tap = j - ic * 9;
        *(__half*)(smem + SM_WOM + oc * RSTRIDE + (tap * 8 + ic) * 2) = __float2half_rn(ow[i]);
    }
    if (tid < 27) ((float*)(smem + SM_BIAS))[tid] = ob[tid];

    uint32_t wa_base = sb + SM_W + (uint32_t)(((wid & 7) * 64 + (lane & 15)) * RSTRIDE) +
                       ((lane >> 4) << 4);
    uint32_t ba4_base = sb + SM_A + (uint32_t)(((lane & 7) + ((lane >> 4) << 3)) * RSTRIDE) +
                        (((lane >> 3) & 1) << 4);
    uint32_t bat_base = sb + SM_A + (uint32_t)(((lane & 7) + (((lane >> 3) & 1) << 3)) * RSTRIDE);
    const float* om_s = (const float*)(smem + SM_OMS);
    __syncthreads();

    // ---- prologue: samplers build A buf0 for tile = blockIdx.x ----
    if (!cons) {
        int pb = blockIdx.x << 6;
        int n0 = pb >> 14, sp0 = pb & 16383;
        for (int rr = sw; rr < 18; rr += 4)
            cp_p(sb, n0, sp0, rr * 32 + lane);
        CP_COMMIT();
        CP_WAIT0();
        BAR_SYNC(6, 128);
        om_gemm(sb, smem, sw, lane);
        BAR_SYNC(6, 128);
        for (int rr = sw; rr < 18; rr += 4)
            gather_task(om_s, n0, sp0, rr * 32 + lane, smem + SM_A);
    }
    __syncthreads();

    int i = 0;
    for (int tile = blockIdx.x; tile < NT; tile += GRID, ++i) {
        int cur = i & 1;
        if (cons) {
            if (i) BAR_SYNC(1 + cur, NTHR);             // FULL: A buf[cur] ready
            int pbase = tile << 6;
            int n = pbase >> 14;
            int spbase = pbase & 16383;
            uint32_t ba4 = ba4_base + (uint32_t)(cur * ABUF);
            uint32_t bat = bat_base + (uint32_t)(cur * ABUF);
#pragma unroll 1
            for (int q = 0; q < 4; q++) {
                int qc = q & 1, qp = q >> 1;
                float acc[2][4][4];
#pragma unroll
                for (int mt = 0; mt < 2; mt++)
#pragma unroll
                    for (int nt = 0; nt < 4; nt++)
#pragma unroll
                        for (int r = 0; r < 4; r++) acc[mt][nt][r] = 0.f;
                mma_hq(wa_base + (uint32_t)(qc * 32 * RSTRIDE),
                       ba4 + (uint32_t)(qp * 32 * RSTRIDE),
                       bat + (uint32_t)(qp * 32 * RSTRIDE), acc);
                epi_hq(acc, out, n, spbase + qp * 32, qc, wid, lane);
            }
            BAR_ARRIVE(4 + cur, NTHR);                  // FREE: done reading buf[cur]
        } else {
            int tp = tile + GRID;
            if (tp < NT) {
                int nxt = cur ^ 1;
                if (i) BAR_SYNC(4 + nxt, NTHR);         // FREE: buf[nxt] reusable
                int pbn = tp << 6;
                int n2 = pbn >> 14;
                int spbn = pbn & 16383;
                for (int rr = sw; rr < 18; rr += 4)
                    cp_p(sb, n2, spbn, rr * 32 + lane);
                CP_COMMIT();
                CP_WAIT0();
                BAR_SYNC(6, 128);                       // P complete (all samplers)
                om_gemm(sb, smem, sw, lane);
                BAR_SYNC(6, 128);                       // om_s complete
                char* bufn = smem + SM_A + nxt * ABUF;
                for (int rr = sw; rr < 18; rr += 4)
                    gather_task(om_s, n2, spbn, rr * 32 + lane, bufn);
                BAR_ARRIVE(1 + nxt, NTHR);              // FULL for next iteration
            }
        }
    }
}

// ---------------- launch ----------------
extern "C" void kernel_launch(void* const* d_in, const int* in_sizes, int n_in,
                              void* d_out, int out_size) {
    const float* x  = (const float*)d_in[0];
    const float* w1 = (const float*)d_in[1];
    const float* b1 = (const float*)d_in[2];
    const float* ow = (const float*)d_in[3];
    const float* ob = (const float*)d_in[4];
    const float* dw = (const float*)d_in[5];
    float* out = (float*)d_out;

    k_conv1<<<(NB * HH * WW / 4 + 255) / 256, 256>>>(x, w1, b1);

    cudaFuncSetAttribute(k_dcn, cudaFuncAttributeMaxDynamicSharedMemorySize, SM_TOTAL);
    k_dcn<<<GRID, NTHR, SM_TOTAL>>>(dw, ow, ob, out);
}

// round 17
// speedup vs baseline: 1.1376x; 1.0532x over previous
#include <cuda_runtime.h>
#include <cuda_fp16.h>
#include <cstdint>

// Shapes (fixed):
//  input_tensor: (8, 3, 256, 256)   d_in[0]
//  conv1_w:      (8, 3, 1, 1)       d_in[1]
//  conv1_b:      (8,)               d_in[2]
//  offset_w:     (27, 8, 3, 3)      d_in[3]
//  offset_b:     (27,)              d_in[4]
//  dcn_w:        (512, 8, 3, 3)     d_in[5]
//  out:          (8, 512, 128, 128) float32

#define NB   8
#define HH   256
#define WW   256
#define HO   128
#define WO   128
#define NPOS (NB * HO * WO)      // 131072
#define TPOS 64
#define NT   (NPOS / TPOS)       // 2048
#define GRID 296
#define NTHR 384                 // 8 consumer warps + 4 sampler warps

typedef unsigned long long u64;

__device__ __half g_y[NB * HH * WW * 8];    // fp16 channels-last, 8 MB

// smem layout (bytes). K=72 rows of 144 B (36 words: conflict-free ldmatrix).
#define RSTRIDE 144
#define SM_W    0                   // W [512][72] fp16              73728
#define SM_A    73728               // A double buf [64][72]         2*9216
#define ABUF    9216
#define SM_P    92160               // P patch [64 pos][72] fp16     9216
#define SM_WOM  101376              // W_om [32 oc][72] fp16         4608
#define SM_OMS  105984              // om_s [28 oc][68 pos] f32      7616
#define SM_BIAS 113600              // offset bias 27 f32 (pad 128)
#define SM_TOTAL 113728

// ------------------------------------------------------------------ PTX utils
__device__ __forceinline__ uint32_t smem_u32(const void* p) {
    uint32_t a;
    asm("{ .reg .u64 t; cvta.to.shared.u64 t, %1; cvt.u32.u64 %0, t; }" : "=r"(a) : "l"(p));
    return a;
}
__device__ __forceinline__ void ldsm4(uint32_t* r, uint32_t a) {
    asm volatile("ldmatrix.sync.aligned.m8n8.x4.shared.b16 {%0,%1,%2,%3}, [%4];"
        : "=r"(r[0]), "=r"(r[1]), "=r"(r[2]), "=r"(r[3]) : "r"(a));
}
__device__ __forceinline__ void ldsm2(uint32_t* r, uint32_t a) {
    asm volatile("ldmatrix.sync.aligned.m8n8.x2.shared.b16 {%0,%1}, [%2];"
        : "=r"(r[0]), "=r"(r[1]) : "r"(a));
}
__device__ __forceinline__ void mma_f16(float* d, const uint32_t* a, const uint32_t* b) {
    asm volatile("mma.sync.aligned.m16n8k16.row.col.f32.f16.f16.f32 "
        "{%0,%1,%2,%3}, {%4,%5,%6,%7}, {%8,%9}, {%0,%1,%2,%3};"
        : "+f"(d[0]), "+f"(d[1]), "+f"(d[2]), "+f"(d[3])
        : "r"(a[0]), "r"(a[1]), "r"(a[2]), "r"(a[3]), "r"(b[0]), "r"(b[1]));
}
__device__ __forceinline__ void mma_f16_k8(float* d, const uint32_t* a, uint32_t b) {
    asm volatile("mma.sync.aligned.m16n8k8.row.col.f32.f16.f16.f32 "
        "{%0,%1,%2,%3}, {%4,%5}, {%6}, {%0,%1,%2,%3};"
        : "+f"(d[0]), "+f"(d[1]), "+f"(d[2]), "+f"(d[3])
        : "r"(a[0]), "r"(a[1]), "r"(b));
}
__device__ __forceinline__ float2 h2f(uint32_t h) {
    __half2 v = *(__half2*)&h;
    return __half22float2(v);
}
__device__ __forceinline__ void cp_async16(uint32_t dst, const void* src, uint32_t src_sz) {
    asm volatile("cp.async.cg.shared.global [%0], [%1], 16, %2;"
        :: "r"(dst), "l"(src), "r"(src_sz) : "memory");
}
#define CP_COMMIT() asm volatile("cp.async.commit_group;" ::: "memory")
#define CP_WAIT0()  asm volatile("cp.async.wait_group 0;" ::: "memory")
#define BAR_SYNC(id, cnt) \
    asm volatile("bar.sync %0, %1;" :: "r"(id), "r"(cnt) : "memory")
#define BAR_ARRIVE(id, cnt) \
    asm volatile("bar.arrive %0, %1;" :: "r"(id), "r"(cnt) : "memory")

// ---------------- kernel 1: 1x1 conv (3->8) + leaky relu -> fp16 channels-last ---------
__global__ void k_conv1(const float* __restrict__ x,
                        const float* __restrict__ w1,
                        const float* __restrict__ b1) {
    int idx4 = blockIdx.x * blockDim.x + threadIdx.x;
    if (idx4 >= NB * HH * WW / 4) return;
    int base = idx4 << 2;
    int n  = base >> 16;
    int hw = base & 0xFFFF;
    float4 c0 = *(const float4*)(x + (size_t)(n * 3 + 0) * 65536 + hw);
    float4 c1 = *(const float4*)(x + (size_t)(n * 3 + 1) * 65536 + hw);
    float4 c2 = *(const float4*)(x + (size_t)(n * 3 + 2) * 65536 + hw);
    float w[24], bb[8];
#pragma unroll
    for (int i = 0; i < 24; i++) w[i] = __ldg(&w1[i]);
#pragma unroll
    for (int i = 0; i < 8; i++) bb[i] = __ldg(&b1[i]);
    float px0[4] = {c0.x, c0.y, c0.z, c0.w};
    float px1[4] = {c1.x, c1.y, c1.z, c1.w};
    float px2[4] = {c2.x, c2.y, c2.z, c2.w};
#pragma unroll
    for (int p = 0; p < 4; p++) {
        uint32_t h[4];
#pragma unroll
        for (int cp = 0; cp < 4; cp++) {
            float t0 = w[(2 * cp) * 3 + 0] * px0[p] + w[(2 * cp) * 3 + 1] * px1[p] +
                       w[(2 * cp) * 3 + 2] * px2[p] + bb[2 * cp];
            float t1 = w[(2 * cp + 1) * 3 + 0] * px0[p] + w[(2 * cp + 1) * 3 + 1] * px1[p] +
                       w[(2 * cp + 1) * 3 + 2] * px2[p] + bb[2 * cp + 1];
            t0 = t0 >= 0.f ? t0 : 0.1f * t0;
            t1 = t1 >= 0.f ? t1 : 0.1f * t1;
            __half2 hh = __floats2half2_rn(t0, t1);
            h[cp] = *(uint32_t*)&hh;
        }
        *(uint4*)(g_y + (size_t)(base + p) * 8) = make_uint4(h[0], h[1], h[2], h[3]);
    }
}

// ---------------- kernel 2: warp-specialized fused DCN -------------------------------
// Warps 0-7 (consumers): 64ch x 64pos x K=72 per warp, processed as 2 position-halves;
// B (sample) fragments register-cached across the 2 channel-halves sharing them
// (consumer ldsm 80 -> 60 per tile). Warps 8-11 (samplers): P cp.async -> om GEMM ->
// gathers (R14 striped maps). Producer/consumer via parity named barriers.

// P task j (0..575): tap = j>>6, pos = j&63 (lanes take consecutive positions)
__device__ __forceinline__ void cp_p(uint32_t sb, int n2, int spbn, int j) {
    int tap = j >> 6, pos = j & 63;
    int sp = spbn + pos;
    int ho = sp >> 7, wo = sp & 127;
    int hy = 2 * ho - 1 + tap / 3;
    int wx = 2 * wo - 1 + tap % 3;
    bool ok = ((unsigned)hy < HH) && ((unsigned)wx < WW);
    int hyc = min(max(hy, 0), HH - 1);
    int wxc = min(max(wx, 0), WW - 1);
    const void* src = g_y + ((size_t)((n2 * HH + hyc) * WW + wxc)) * 8;
    uint32_t dst = sb + SM_P + (uint32_t)(pos * RSTRIDE + tap * 16);
    cp_async16(dst, src, ok ? 16u : 0u);
}

// om GEMM: sampler warp sw computes 32 oc x 16 pos (pos sw*16..sw*16+15).
__device__ __forceinline__ void om_gemm(uint32_t sb, char* smem, int sw, int lane) {
    int g = lane >> 2, tg = lane & 3;
    float aco[2][2][4];
#pragma unroll
    for (int mt = 0; mt < 2; mt++)
#pragma unroll
        for (int nt = 0; nt < 2; nt++)
#pragma unroll
            for (int r = 0; r < 4; r++) aco[mt][nt][r] = 0.f;
    uint32_t wa = sb + SM_WOM + (uint32_t)((lane & 15) * RSTRIDE) + ((lane >> 4) << 4);
    uint32_t bp = sb + SM_P +
                  (uint32_t)((sw * 16 + (lane & 7) + ((lane >> 4) << 3)) * RSTRIDE) +
                  (((lane >> 3) & 1) << 4);
#pragma unroll
    for (int ks = 0; ks < 4; ks++) {
        uint32_t a0[4], a1[4], bo[4];
        ldsm4(a0, wa + ks * 32);
        ldsm4(a1, wa + (uint32_t)(16 * RSTRIDE) + ks * 32);
        ldsm4(bo, bp + ks * 32);
        mma_f16(aco[0][0], a0, bo);
        mma_f16(aco[0][1], a0, bo + 2);
        mma_f16(aco[1][0], a1, bo);
        mma_f16(aco[1][1], a1, bo + 2);
    }
    // k8 tail (kk 64..71)
    {
        uint32_t a0t[2], a1t[2], bt[2];
        ldsm2(a0t, wa + 128);
        ldsm2(a1t, wa + (uint32_t)(16 * RSTRIDE) + 128);
        uint32_t btp = sb + SM_P +
                       (uint32_t)((sw * 16 + (lane & 7) + (((lane >> 3) & 1) << 3)) * RSTRIDE);
        ldsm2(bt, btp + 128);
        mma_f16_k8(aco[0][0], a0t, bt[0]);
        mma_f16_k8(aco[0][1], a0t, bt[1]);
        mma_f16_k8(aco[1][0], a1t, bt[0]);
        mma_f16_k8(aco[1][1], a1t, bt[1]);
    }

    float* om_s = (float*)(smem + SM_OMS);
    const float* bias = (const float*)(smem + SM_BIAS);
#pragma unroll
    for (int mt = 0; mt < 2; mt++)
#pragma unroll
        for (int r = 0; r < 2; r++) {
            int oc = mt * 16 + g + 8 * r;
            if (oc < 27) {
#pragma unroll
                for (int nt = 0; nt < 2; nt++)
#pragma unroll
                    for (int c = 0; c < 2; c++) {
                        int pos = sw * 16 + nt * 8 + 2 * tg + c;
                        float v = aco[mt][nt][2 * r + c] + bias[oc];
                        if (oc >= 18) v = 1.f / (1.f + __expf(-v));
                        om_s[oc * 68 + pos] = v;
                    }
            }
        }
}

// consumer: run one 32ch x 32pos quarter against register-cached B fragments
__device__ __forceinline__ void mma_qc(uint32_t wa, const uint32_t* bq,
                                       float acc[2][4][4]) {
#pragma unroll
    for (int ks = 0; ks < 4; ks++) {
        uint32_t a0[4], a1[4];
        ldsm4(a0, wa + ks * 32);
        ldsm4(a1, wa + (uint32_t)(16 * RSTRIDE) + ks * 32);
        const uint32_t* b = bq + ks * 8;
#pragma unroll
        for (int p = 0; p < 2; p++) {
            mma_f16(acc[0][2 * p],     a0, b + p * 4);
            mma_f16(acc[0][2 * p + 1], a0, b + p * 4 + 2);
            mma_f16(acc[1][2 * p],     a1, b + p * 4);
            mma_f16(acc[1][2 * p + 1], a1, b + p * 4 + 2);
        }
    }
    uint32_t a0t[2], a1t[2];
    ldsm2(a0t, wa + 128);
    ldsm2(a1t, wa + (uint32_t)(16 * RSTRIDE) + 128);
#pragma unroll
    for (int p = 0; p < 2; p++) {
        mma_f16_k8(acc[0][2 * p],     a0t, bq[32 + 2 * p]);
        mma_f16_k8(acc[0][2 * p + 1], a0t, bq[32 + 2 * p + 1]);
        mma_f16_k8(acc[1][2 * p],     a1t, bq[32 + 2 * p]);
        mma_f16_k8(acc[1][2 * p + 1], a1t, bq[32 + 2 * p + 1]);
    }
}

// epilogue for one 32ch x 32pos quarter: shfl-assembled STG.128
__device__ __forceinline__ void epi_hq(const float acc[2][4][4], float* out,
                                       int n, int spq, int qc,
                                       int wid, int lane) {
    int g = lane >> 2, tg = lane & 3;
    int odd = tg & 1;
#pragma unroll
    for (int mt = 0; mt < 2; mt++) {
        int ch0 = wid * 64 + qc * 32 + mt * 16 + g;
#pragma unroll
        for (int r = 0; r < 2; r++) {
            float* rowp = out + (size_t)(n * 512 + ch0 + 8 * r) * 16384 + spq;
#pragma unroll
            for (int p = 0; p < 2; p++) {
                int nt0 = 2 * p, nt1 = 2 * p + 1;
                float a0x = acc[mt][nt0][2 * r], a0y = acc[mt][nt0][2 * r + 1];
                float a1x = acc[mt][nt1][2 * r], a1y = acc[mt][nt1][2 * r + 1];
                u64 send = odd
                    ? (((u64)__float_as_uint(a0y) << 32) | __float_as_uint(a0x))
                    : (((u64)__float_as_uint(a1y) << 32) | __float_as_uint(a1x));
                u64 recv = __shfl_xor_sync(0xffffffffu, send, 1);
                float rx = __uint_as_float((uint32_t)recv);
                float ry = __uint_as_float((uint32_t)(recv >> 32));
                float4 v = odd ? make_float4(rx, ry, a1x, a1y)
                               : make_float4(a0x, a0y, rx, ry);
                int col = (odd ? nt1 : nt0) * 8 + (tg >> 1) * 4;
                __stcs((float4*)(rowp + col), v);
            }
        }
    }
}

// gather one (pos,k) task: read om_s, 4 bilinear LDGs, convert, STS
__device__ __forceinline__ void gather_task(const float* om_s, int n2, int spbn, int t,
                                            char* bufn) {
    int pos = t & 63, k = t >> 6;
    float dy = om_s[(2 * k) * 68 + pos];
    float dx = om_s[(2 * k + 1) * 68 + pos];
    float m  = om_s[(18 + k) * 68 + pos];
    int sp = spbn + pos;
    int ho = sp >> 7, wo = sp & 127;
    int ky = k / 3, kx = k - ky * 3;
    float py = (float)(2 * ho - 1 + ky) + dy;
    float px = (float)(2 * wo - 1 + kx) + dx;
    float y0f = floorf(py), x0f = floorf(px);
    float fy = py - y0f, fx = px - x0f;
    int y0 = (int)y0f, x0 = (int)x0f;
    uint4 q[4];
    float w4[4];
#pragma unroll
    for (int oy = 0; oy < 2; oy++) {
        int yy = y0 + oy;
        float wy = (oy ? fy : 1.f - fy) * ((unsigned)yy < HH ? 1.f : 0.f);
        int yc = min(max(yy, 0), HH - 1);
#pragma unroll
        for (int ox = 0; ox < 2; ox++) {
            int xx = x0 + ox;
            float wgt = wy * (ox ? fx : 1.f - fx) * ((unsigned)xx < WW ? 1.f : 0.f);
            int xc = min(max(xx, 0), WW - 1);
            w4[oy * 2 + ox] = wgt;
            q[oy * 2 + ox] = *(const uint4*)(g_y + ((size_t)((n2 * HH + yc) * WW + xc)) * 8);
        }
    }
    float a[8] = {0, 0, 0, 0, 0, 0, 0, 0};
#pragma unroll
    for (int cor = 0; cor < 4; cor++) {
        float wgt = w4[cor];
        float2 f0 = h2f(q[cor].x), f1 = h2f(q[cor].y);
        float2 f2 = h2f(q[cor].z), f3 = h2f(q[cor].w);
        a[0] += wgt * f0.x; a[1] += wgt * f0.y; a[2] += wgt * f1.x; a[3] += wgt * f1.y;
        a[4] += wgt * f2.x; a[5] += wgt * f2.y; a[6] += wgt * f3.x; a[7] += wgt * f3.y;
    }
    uint32_t h4[4];
#pragma unroll
    for (int i = 0; i < 4; i++) {
        __half2 h = __floats2half2_rn(a[2 * i] * m, a[2 * i + 1] * m);
        h4[i] = *(uint32_t*)&h;
    }
    *(uint4*)(bufn + pos * RSTRIDE + k * 16) = make_uint4(h4[0], h4[1], h4[2], h4[3]);
}

__global__ void __launch_bounds__(NTHR, 2)
k_dcn(const float* __restrict__ dw,
      const float* __restrict__ ow, const float* __restrict__ ob,
      float* __restrict__ out) {
    extern __shared__ char smem[];
    uint32_t sb = smem_u32(smem);
    int tid = threadIdx.x, lane = tid & 31, wid = tid >> 5;
    bool cons = (wid < 8);
    int sw = wid - 8;

    // W fill: W[ch][kk] fp16, kk = tap*8 + c
    for (int i = tid; i < 512 * 72; i += NTHR) {
        int ch = i / 72, j = i - ch * 72;      // j = c*9 + tap
        int c = j / 9, k = j - c * 9;
        *(__half*)(smem + SM_W + ch * RSTRIDE + (k * 8 + c) * 2) = __float2half_rn(dw[i]);
    }
    // W_om: zero pad rows then fill [oc][kk = tap*8 + ic]
    for (int i = tid; i < 4608 / 16; i += NTHR)
        ((uint4*)(smem + SM_WOM))[i] = make_uint4(0, 0, 0, 0);
    __syncthreads();
    for (int i = tid; i < 27 * 72; i += NTHR) {
        int oc = i / 72, j = i - oc * 72;      // j = ic*9 + tap
        int ic = j / 9, tap = j - ic * 9;
        *(__half*)(smem + SM_WOM + oc * RSTRIDE + (tap * 8 + ic) * 2) = __float2half_rn(ow[i]);
    }
    if (tid < 27) ((float*)(smem + SM_BIAS))[tid] = ob[tid];

    uint32_t wa_base = sb + SM_W + (uint32_t)(((wid & 7) * 64 + (lane & 15)) * RSTRIDE) +
                       ((lane >> 4) << 4);
    uint32_t ba4_base = sb + SM_A + (uint32_t)(((lane & 7) + ((lane >> 4) << 3)) * RSTRIDE) +
                        (((lane >> 3) & 1) << 4);
    uint32_t bat_base = sb + SM_A + (uint32_t)(((lane & 7) + (((lane >> 3) & 1) << 3)) * RSTRIDE);
    const float* om_s = (const float*)(smem + SM_OMS);
    __syncthreads();

    // ---- prologue: samplers build A buf0 for tile = blockIdx.x ----
    if (!cons) {
        int pb = blockIdx.x << 6;
        int n0 = pb >> 14, sp0 = pb & 16383;
        for (int rr = sw; rr < 18; rr += 4)
            cp_p(sb, n0, sp0, rr * 32 + lane);
        CP_COMMIT();
        CP_WAIT0();
        BAR_SYNC(6, 128);
        om_gemm(sb, smem, sw, lane);
        BAR_SYNC(6, 128);
        for (int rr = sw; rr < 18; rr += 4)
            gather_task(om_s, n0, sp0, rr * 32 + lane, smem + SM_A);
    }
    __syncthreads();

    int i = 0;
    for (int tile = blockIdx.x; tile < NT; tile += GRID, ++i) {
        int cur = i & 1;
        if (cons) {
            if (i) BAR_SYNC(1 + cur, NTHR);             // FULL: A buf[cur] ready
            int pbase = tile << 6;
            int n = pbase >> 14;
            int spbase = pbase & 16383;
            uint32_t ba4 = ba4_base + (uint32_t)(cur * ABUF);
            uint32_t bat = bat_base + (uint32_t)(cur * ABUF);
#pragma unroll 1
            for (int qp = 0; qp < 2; qp++) {
                // load B fragments for this 32-pos half ONCE (reused by both qc)
                uint32_t bq[36];
                uint32_t ba4q = ba4 + (uint32_t)(qp * 32 * RSTRIDE);
                uint32_t batq = bat + (uint32_t)(qp * 32 * RSTRIDE);
#pragma unroll
                for (int ks = 0; ks < 4; ks++) {
                    ldsm4(bq + ks * 8,     ba4q + ks * 32);
                    ldsm4(bq + ks * 8 + 4, ba4q + (uint32_t)(16 * RSTRIDE) + ks * 32);
                }
                ldsm2(bq + 32, batq + 128);
                ldsm2(bq + 34, batq + (uint32_t)(16 * RSTRIDE) + 128);
#pragma unroll 1
                for (int qc = 0; qc < 2; qc++) {
                    float acc[2][4][4];
#pragma unroll
                    for (int mt = 0; mt < 2; mt++)
#pragma unroll
                        for (int nt = 0; nt < 4; nt++)
#pragma unroll
                            for (int r = 0; r < 4; r++) acc[mt][nt][r] = 0.f;
                    mma_qc(wa_base + (uint32_t)(qc * 32 * RSTRIDE), bq, acc);
                    epi_hq(acc, out, n, spbase + qp * 32, qc, wid, lane);
                }
            }
            BAR_ARRIVE(4 + cur, NTHR);                  // FREE: done reading buf[cur]
        } else {
            int tp = tile + GRID;
            if (tp < NT) {
                int nxt = cur ^ 1;
                if (i) BAR_SYNC(4 + nxt, NTHR);         // FREE: buf[nxt] reusable
                int pbn = tp << 6;
                int n2 = pbn >> 14;
                int spbn = pbn & 16383;
                for (int rr = sw; rr < 18; rr += 4)
                    cp_p(sb, n2, spbn, rr * 32 + lane);
                CP_COMMIT();
                CP_WAIT0();
                BAR_SYNC(6, 128);                       // P complete (all samplers)
                om_gemm(sb, smem, sw, lane);
                BAR_SYNC(6, 128);                       // om_s complete
                char* bufn = smem + SM_A + nxt * ABUF;
                for (int rr = sw; rr < 18; rr += 4)
                    gather_task(om_s, n2, spbn, rr * 32 + lane, bufn);
                BAR_ARRIVE(1 + nxt, NTHR);              // FULL for next iteration
            }
        }
    }
}

// ---------------- launch ----------------
extern "C" void kernel_launch(void* const* d_in, const int* in_sizes, int n_in,
                              void* d_out, int out_size) {
    const float* x  = (const float*)d_in[0];
    const float* w1 = (const float*)d_in[1];
    const float* b1 = (const float*)d_in[2];
    const float* ow = (const float*)d_in[3];
    const float* ob = (const float*)d_in[4];
    const float* dw = (const float*)d_in[5];
    float* out = (float*)d_out;

    k_conv1<<<(NB * HH * WW / 4 + 255) / 256, 256>>>(x, w1, b1);

    cudaFuncSetAttribute(k_dcn, cudaFuncAttributeMaxDynamicSharedMemorySize, SM_TOTAL);
    k_dcn<<<GRID, NTHR, SM_TOTAL>>>(dw, ow, ob, out);
}